// round 9
// baseline (speedup 1.0000x reference)
#include <cuda_runtime.h>
#include <cuda_fp16.h>

#define B_    8
#define SENC  256
#define SDEC  128
#define U_    512
#define DIM   512

// ------------------------- scratch (device globals, no alloc) -------------
__device__ __align__(16) __half g_denc_h[B_ * SENC * U_];   // 2 MB
__device__ __align__(16) __half g_ddec_h[B_ * SDEC * U_];   // 1 MB
__device__ __align__(16) __half g_wh[U_];

// ------------------------- helpers ----------------------------------------
__device__ __forceinline__ __half2 atk_tanh_h2(__half2 x) {
    __half2 y;
    asm("tanh.approx.f16x2 %0, %1;"
        : "=r"(reinterpret_cast<unsigned&>(y))
        : "r"(reinterpret_cast<unsigned const&>(x)));
    return y;
}

// ------------------------- GEMM: C(half) = A[M,512] @ W[512,512] + bias ----
// BM=BN=64, BK=16, 256 threads, 4x4 micro-tile. (At FFMA roofline; replaced
// by tensor cores in a later round.)
__global__ void __launch_bounds__(256) sgemm_bias_half(
    const float* __restrict__ A, const float* __restrict__ W,
    const float* __restrict__ bias, int which /*0->g_denc_h, 1->g_ddec_h*/)
{
    __half* __restrict__ C = which ? g_ddec_h : g_denc_h;
    const int N = 512, K = 512;
    __shared__ float As[16][68];
    __shared__ float Bs[16][68];

    int t  = threadIdx.x;
    int tx = t & 15, ty = t >> 4;
    int bm = blockIdx.x * 64, bn = blockIdx.y * 64;

    int ar = t >> 2, ac = (t & 3) << 2;
    int br = t >> 4, bc = (t & 15) << 2;

    const float* Ag = A + (size_t)(bm + ar) * K + ac;
    const float* Wg = W + (size_t)br * N + bn + bc;

    float acc[4][4] = {};

    for (int k0 = 0; k0 < K; k0 += 16) {
        float4 av = *(const float4*)(Ag + k0);
        float4 bv = *(const float4*)(Wg + (size_t)k0 * N);
        As[ac + 0][ar] = av.x; As[ac + 1][ar] = av.y;
        As[ac + 2][ar] = av.z; As[ac + 3][ar] = av.w;
        *(float4*)&Bs[br][bc] = bv;
        __syncthreads();
#pragma unroll
        for (int kk = 0; kk < 16; kk++) {
            float a[4], b[4];
            *(float4*)a = *(const float4*)&As[kk][ty << 2];
            *(float4*)b = *(const float4*)&Bs[kk][tx << 2];
#pragma unroll
            for (int i = 0; i < 4; i++)
#pragma unroll
                for (int j = 0; j < 4; j++)
                    acc[i][j] = fmaf(a[i], b[j], acc[i][j]);
        }
        __syncthreads();
    }

#pragma unroll
    for (int j = 0; j < 4; j++) {
        float bj = bias[bn + (tx << 2) + j];
#pragma unroll
        for (int i = 0; i < 4; i++) {
            int row = bm + (ty << 2) + i;
            C[(size_t)row * N + bn + (tx << 2) + j] =
                __float2half_rn(acc[i][j] + bj);
        }
    }
}

// ------------------------- W_score fp32 -> fp16 ----------------------------
__global__ void wconv(const float* __restrict__ ws)
{
    int i = blockIdx.x * 256 + threadIdx.x;
    if (i < U_) g_wh[i] = __float2half_rn(ws[i]);
}

// ------------------------- fused scores + softmax + context ----------------
// Block = (b, q-group of 4). 512 threads = 16 warps; 4 warps per q.
// Warp (wq,p) handles e in [p*16, p*16+16) of each 64-row tile, processing
// 4 e concurrently for ILP on the tanh and shuffle-reduce chains.
#define ETILE  64   // d_enc rows per smem tile (fp16): 64*512*2 = 64 KB
#define E2TILE 32   // enc rows per smem tile (fp32): 32*512*4 = 64 KB

extern __shared__ char smem_raw[];

__global__ void __launch_bounds__(512) fused_attn(
    const float* __restrict__ enc, float* __restrict__ out)
{
    __half2* s_de  = (__half2*)smem_raw;            // [ETILE*256] half2
    float*   s_enc = (float*)smem_raw;              // union: [E2TILE*512]
    float*   s_w   = (float*)(smem_raw + 65536);    // [4*256] scores->weights
    __shared__ float s_red[32];

    int t  = threadIdx.x;
    int l  = t & 31, w = t >> 5;          // 16 warps
    int qg = blockIdx.x, b = blockIdx.y;
    int wq = w >> 2, p = w & 3;           // q within group, quarter
    int qrow = b * SDEC + qg * 4 + wq;

    // per-lane decoder projection + score weights (half2, interleaved layout)
    __half2 dd2[8], wv[8];
    {
        const __half2* ddp = (const __half2*)g_ddec_h + (size_t)qrow * 256;
        const __half2* wp  = (const __half2*)g_wh;
#pragma unroll
        for (int j = 0; j < 8; j++) {
            dd2[j] = ddp[l + 32 * j];
            wv[j]  = wp[l + 32 * j];
        }
    }

    // ---- phase 1: scores ----
    const uint4* de_g = (const uint4*)(g_denc_h + (size_t)b * SENC * U_);
    for (int et = 0; et < SENC / ETILE; et++) {
        __syncthreads();
        {
            const uint4* src = de_g + (size_t)et * ETILE * 64;
            uint4* dst = (uint4*)s_de;
#pragma unroll
            for (int i = 0; i < (ETILE * 64) / 512; i++)
                dst[t + 512 * i] = src[t + 512 * i];
        }
        __syncthreads();
#pragma unroll
        for (int eg = 0; eg < 4; eg++) {      // 4 groups of 4 concurrent e
            int e0 = p * 16 + eg * 4;
            float s0, s1, s2, s3;
            {
                __half2 b0a = __float2half2_rn(0.f), b0b = b0a;
                __half2 b1a = b0a, b1b = b0a;
                __half2 b2a = b0a, b2b = b0a;
                __half2 b3a = b0a, b3b = b0a;
                const __half2* d0 = s_de + (e0 + 0) * 256;
                const __half2* d1 = s_de + (e0 + 1) * 256;
                const __half2* d2 = s_de + (e0 + 2) * 256;
                const __half2* d3 = s_de + (e0 + 3) * 256;
#pragma unroll
                for (int j = 0; j < 8; j++) {
                    __half2 dd = dd2[j], wj = wv[j];
                    __half2 t0 = atk_tanh_h2(__hadd2(dd, d0[l + 32 * j]));
                    __half2 t1 = atk_tanh_h2(__hadd2(dd, d1[l + 32 * j]));
                    __half2 t2 = atk_tanh_h2(__hadd2(dd, d2[l + 32 * j]));
                    __half2 t3 = atk_tanh_h2(__hadd2(dd, d3[l + 32 * j]));
                    if (j & 1) {
                        b0b = __hfma2(t0, wj, b0b); b1b = __hfma2(t1, wj, b1b);
                        b2b = __hfma2(t2, wj, b2b); b3b = __hfma2(t3, wj, b3b);
                    } else {
                        b0a = __hfma2(t0, wj, b0a); b1a = __hfma2(t1, wj, b1a);
                        b2a = __hfma2(t2, wj, b2a); b3a = __hfma2(t3, wj, b3a);
                    }
                }
                float2 u, v;
                u = __half22float2(b0a); v = __half22float2(b0b);
                s0 = (u.x + u.y) + (v.x + v.y);
                u = __half22float2(b1a); v = __half22float2(b1b);
                s1 = (u.x + u.y) + (v.x + v.y);
                u = __half22float2(b2a); v = __half22float2(b2b);
                s2 = (u.x + u.y) + (v.x + v.y);
                u = __half22float2(b3a); v = __half22float2(b3b);
                s3 = (u.x + u.y) + (v.x + v.y);
            }
            // 4 independent butterfly chains (interleaved by scheduler)
#pragma unroll
            for (int o = 16; o > 0; o >>= 1) {
                s0 += __shfl_xor_sync(0xffffffffu, s0, o);
                s1 += __shfl_xor_sync(0xffffffffu, s1, o);
                s2 += __shfl_xor_sync(0xffffffffu, s2, o);
                s3 += __shfl_xor_sync(0xffffffffu, s3, o);
            }
            if (l == 0) {
                float* dst = s_w + wq * 256 + et * ETILE + e0;
                dst[0] = s0; dst[1] = s1; dst[2] = s2; dst[3] = s3;
            }
        }
    }
    __syncthreads();

    // ---- softmax over 256 encoder positions, 128 threads per q ----
    int qs = t >> 7, idx = t & 127;
    float v0 = s_w[qs * 256 + idx], v1 = s_w[qs * 256 + idx + 128];
    float m = fmaxf(v0, v1);
#pragma unroll
    for (int o = 16; o > 0; o >>= 1)
        m = fmaxf(m, __shfl_xor_sync(0xffffffffu, m, o));
    if (l == 0) s_red[w] = m;
    __syncthreads();
    m = fmaxf(fmaxf(s_red[qs * 4], s_red[qs * 4 + 1]),
              fmaxf(s_red[qs * 4 + 2], s_red[qs * 4 + 3]));
    float e0 = __expf(v0 - m), e1 = __expf(v1 - m);
    float sum = e0 + e1;
#pragma unroll
    for (int o = 16; o > 0; o >>= 1)
        sum += __shfl_xor_sync(0xffffffffu, sum, o);
    if (l == 0) s_red[16 + w] = sum;
    __syncthreads();
    float inv = 1.f / (s_red[16 + qs * 4] + s_red[16 + qs * 4 + 1] +
                       s_red[16 + qs * 4 + 2] + s_red[16 + qs * 4 + 3]);
    s_w[qs * 256 + idx]       = e0 * inv;
    s_w[qs * 256 + idx + 128] = e1 * inv;

    // ---- phase 2: contexts = weights @ encodings ----
    // thread owns q2 = t>>7, dims [g*4, g*4+4)
    int q2 = qs, g = idx;
    float acc0[4] = {};
    const float* encb = enc + (size_t)b * SENC * DIM;
    for (int et = 0; et < SENC / E2TILE; et++) {
        __syncthreads();   // orders weight writes & smem union reuse
        {
            const float4* src = (const float4*)(encb + (size_t)et * E2TILE * DIM);
            float4* dst = (float4*)s_enc;
#pragma unroll
            for (int i = 0; i < (E2TILE * DIM / 4) / 512; i++)
                dst[t + 512 * i] = src[t + 512 * i];
        }
        __syncthreads();
#pragma unroll 4
        for (int el = 0; el < E2TILE; el++) {
            float wgt = s_w[q2 * 256 + et * E2TILE + el];
            const float* er = s_enc + el * DIM;
            float4 x0 = *(const float4*)(er + g * 4);
            acc0[0] = fmaf(wgt, x0.x, acc0[0]);
            acc0[1] = fmaf(wgt, x0.y, acc0[1]);
            acc0[2] = fmaf(wgt, x0.z, acc0[2]);
            acc0[3] = fmaf(wgt, x0.w, acc0[3]);
        }
    }

    float* orow = out + (size_t)(b * SDEC + qg * 4 + q2) * DIM;
    *(float4*)(orow + g * 4) = make_float4(acc0[0], acc0[1], acc0[2], acc0[3]);
}

// ------------------------- launch ------------------------------------------
extern "C" void kernel_launch(void* const* d_in, const int* in_sizes, int n_in,
                              void* d_out, int out_size)
{
    (void)in_sizes; (void)n_in; (void)out_size;
    const float* enc    = (const float*)d_in[0];
    const float* dec    = (const float*)d_in[1];
    const float* Wenc   = (const float*)d_in[2];
    const float* Wdec   = (const float*)d_in[3];
    const float* Wscore = (const float*)d_in[4];
    const float* benc   = (const float*)d_in[5];
    const float* bdec   = (const float*)d_in[6];
    float* out = (float*)d_out;

    // projections -> fp16 scratch
    sgemm_bias_half<<<dim3((B_ * SENC) / 64, U_ / 64), 256>>>(enc, Wenc, benc, 0);
    sgemm_bias_half<<<dim3((B_ * SDEC) / 64, U_ / 64), 256>>>(dec, Wdec, bdec, 1);
    wconv<<<2, 256>>>(Wscore);

    const int SMEM = 65536 + 4096;  // de/enc tile union + weights
    cudaFuncSetAttribute(fused_attn,
                         cudaFuncAttributeMaxDynamicSharedMemorySize, SMEM);
    fused_attn<<<dim3(SDEC / 4, B_), 512, SMEM>>>(enc, out);
}

// round 13
// speedup vs baseline: 1.0931x; 1.0931x over previous
#include <cuda_runtime.h>
#include <cuda_fp16.h>

#define B_    8
#define SENC  256
#define SDEC  128
#define U_    512
#define DIM   512

#define QG     2      // decoder positions per block
#define ETILE  32     // phase-1 tile rows (fp16): 32*512*2 = 32 KB
#define FTILE  16     // phase-2 tile rows (fp32): 16*512*4 = 32 KB
#define BUFB   32768

// ------------------------- scratch (device globals, no alloc) -------------
__device__ __align__(16) __half g_denc_h[B_ * SENC * U_];   // 2 MB
__device__ __align__(16) __half g_ddec_h[B_ * SDEC * U_];   // 1 MB

// ------------------------- helpers ----------------------------------------
__device__ __forceinline__ __half2 atk_tanh_h2(__half2 x) {
    __half2 y;
    asm("tanh.approx.f16x2 %0, %1;"
        : "=r"(reinterpret_cast<unsigned&>(y))
        : "r"(reinterpret_cast<unsigned const&>(x)));
    return y;
}
__device__ __forceinline__ unsigned smem_u32(const void* p) {
    return (unsigned)__cvta_generic_to_shared(p);
}
__device__ __forceinline__ void cp16(unsigned dst, const void* src) {
    asm volatile("cp.async.cg.shared.global [%0], [%1], 16;" :: "r"(dst), "l"(src));
}
__device__ __forceinline__ void cp_commit() {
    asm volatile("cp.async.commit_group;" ::);
}
template<int N> __device__ __forceinline__ void cp_wait() {
    asm volatile("cp.async.wait_group %0;" :: "n"(N));
}

// ------------- merged projections: 2 GEMMs, one launch ---------------------
// bx<32: enc rows (2048/64), else dec rows (1024/64). BM=BN=64, BK=16.
__global__ void __launch_bounds__(256) proj2(
    const float* __restrict__ enc, const float* __restrict__ dec,
    const float* __restrict__ Wenc, const float* __restrict__ Wdec,
    const float* __restrict__ benc, const float* __restrict__ bdec)
{
    const int N = 512, K = 512;
    __shared__ float As[16][68];
    __shared__ float Bs[16][68];

    int bx = blockIdx.x;
    const float* A; const float* W; const float* bias; __half* C; int bm;
    if (bx < 32) { A = enc; W = Wenc; bias = benc; C = g_denc_h; bm = bx * 64; }
    else         { A = dec; W = Wdec; bias = bdec; C = g_ddec_h; bm = (bx - 32) * 64; }

    int t  = threadIdx.x;
    int tx = t & 15, ty = t >> 4;
    int bn = blockIdx.y * 64;

    int ar = t >> 2, ac = (t & 3) << 2;
    int br = t >> 4, bc = (t & 15) << 2;

    const float* Ag = A + (size_t)(bm + ar) * K + ac;
    const float* Wg = W + (size_t)br * N + bn + bc;

    float acc[4][4] = {};

    for (int k0 = 0; k0 < K; k0 += 16) {
        float4 av = *(const float4*)(Ag + k0);
        float4 bv = *(const float4*)(Wg + (size_t)k0 * N);
        As[ac + 0][ar] = av.x; As[ac + 1][ar] = av.y;
        As[ac + 2][ar] = av.z; As[ac + 3][ar] = av.w;
        *(float4*)&Bs[br][bc] = bv;
        __syncthreads();
#pragma unroll
        for (int kk = 0; kk < 16; kk++) {
            float a[4], b[4];
            *(float4*)a = *(const float4*)&As[kk][ty << 2];
            *(float4*)b = *(const float4*)&Bs[kk][tx << 2];
#pragma unroll
            for (int i = 0; i < 4; i++)
#pragma unroll
                for (int j = 0; j < 4; j++)
                    acc[i][j] = fmaf(a[i], b[j], acc[i][j]);
        }
        __syncthreads();
    }

#pragma unroll
    for (int j = 0; j < 4; j++) {
        float bj = bias[bn + (tx << 2) + j];
#pragma unroll
        for (int i = 0; i < 4; i++) {
            int row = bm + (ty << 2) + i;
            C[(size_t)row * N + bn + (tx << 2) + j] =
                __float2half_rn(acc[i][j] + bj);
        }
    }
}

// ------------------------- fused scores + softmax + context ----------------
// Block = (b, q-pair). 256 threads = 8 warps; 4 warps per q.
// Lane l owns u [8l,8l+8) and [256+8l,256+8l+8)  (two 16B chunks per e-row).
extern __shared__ char smem_raw[];

__global__ void __launch_bounds__(256) fused_attn(
    const float* __restrict__ enc, const float* __restrict__ Wscore,
    float* __restrict__ out)
{
    char* buf[2] = { smem_raw, smem_raw + BUFB };
    float* s_w = (float*)(smem_raw + 2 * BUFB);       // [QG*256]
    __shared__ float s_red[16];

    int t  = threadIdx.x;
    int l  = t & 31, w = t >> 5;
    int qg = blockIdx.x, b = blockIdx.y;
    int wq = w >> 2, p = w & 3;
    int qrow = b * SDEC + qg * QG + wq;

    unsigned sb[2] = { smem_u32(buf[0]), smem_u32(buf[1]) };

    // decoder projection (fp16) + score weights (fp32->fp16), contiguous layout
    __half2 dd2[8], wv[8];
    {
        const uint4* ddp4 = (const uint4*)(g_ddec_h + (size_t)qrow * U_);
        uint4 a0 = ddp4[l], a1 = ddp4[32 + l];
        *(uint4*)&dd2[0] = a0;
        *(uint4*)&dd2[4] = a1;
        const float4* wsp = (const float4*)Wscore;
        float4 w0 = wsp[2 * l], w1 = wsp[2 * l + 1];
        float4 w2 = wsp[64 + 2 * l], w3 = wsp[64 + 2 * l + 1];
        wv[0] = __floats2half2_rn(w0.x, w0.y);
        wv[1] = __floats2half2_rn(w0.z, w0.w);
        wv[2] = __floats2half2_rn(w1.x, w1.y);
        wv[3] = __floats2half2_rn(w1.z, w1.w);
        wv[4] = __floats2half2_rn(w2.x, w2.y);
        wv[5] = __floats2half2_rn(w2.z, w2.w);
        wv[6] = __floats2half2_rn(w3.x, w3.y);
        wv[7] = __floats2half2_rn(w3.z, w3.w);
    }

    // ---- phase 1: scores (double-buffered cp.async) ----
    const char* de_g = (const char*)(g_denc_h + (size_t)b * SENC * U_);
    const int NT1 = SENC / ETILE;   // 8

    {   // prefetch tile 0
        const char* src = de_g;
#pragma unroll
        for (int i = 0; i < 8; i++)
            cp16(sb[0] + (t + 256 * i) * 16, src + (size_t)(t + 256 * i) * 16);
        cp_commit();
    }

    for (int et = 0; et < NT1; et++) {
        if (et + 1 < NT1) {   // prefetch next into other buffer
            const char* src = de_g + (size_t)(et + 1) * ETILE * U_ * 2;
            unsigned d = sb[(et + 1) & 1];
#pragma unroll
            for (int i = 0; i < 8; i++)
                cp16(d + (t + 256 * i) * 16, src + (size_t)(t + 256 * i) * 16);
            cp_commit();
            cp_wait<1>();
        } else {
            cp_wait<0>();
        }
        __syncthreads();
        const __half2* s_de = (const __half2*)buf[et & 1];

#pragma unroll
        for (int eg = 0; eg < 2; eg++) {
            int e0 = p * 8 + eg * 4;
            uint4 va[4], vb[4];
#pragma unroll
            for (int k = 0; k < 4; k++) {
                const uint4* row = (const uint4*)(s_de + (size_t)(e0 + k) * 256);
                va[k] = row[l];
                vb[k] = row[32 + l];
            }
            __half2 z = __float2half2_rn(0.f);
            __half2 aA[4] = { z, z, z, z }, aB[4] = { z, z, z, z };
#pragma unroll
            for (int j = 0; j < 4; j++) {
                __half2 dd = dd2[j], wj = wv[j];
#pragma unroll
                for (int k = 0; k < 4; k++) {
                    __half2 de = ((const __half2*)&va[k])[j];
                    __half2 th = atk_tanh_h2(__hadd2(dd, de));
                    if (j & 1) aB[k] = __hfma2(th, wj, aB[k]);
                    else       aA[k] = __hfma2(th, wj, aA[k]);
                }
            }
#pragma unroll
            for (int j = 0; j < 4; j++) {
                __half2 dd = dd2[4 + j], wj = wv[4 + j];
#pragma unroll
                for (int k = 0; k < 4; k++) {
                    __half2 de = ((const __half2*)&vb[k])[j];
                    __half2 th = atk_tanh_h2(__hadd2(dd, de));
                    if (j & 1) aB[k] = __hfma2(th, wj, aB[k]);
                    else       aA[k] = __hfma2(th, wj, aA[k]);
                }
            }
            float s0, s1, s2, s3;
            {
                float2 u, v;
                u = __half22float2(aA[0]); v = __half22float2(aB[0]);
                s0 = (u.x + u.y) + (v.x + v.y);
                u = __half22float2(aA[1]); v = __half22float2(aB[1]);
                s1 = (u.x + u.y) + (v.x + v.y);
                u = __half22float2(aA[2]); v = __half22float2(aB[2]);
                s2 = (u.x + u.y) + (v.x + v.y);
                u = __half22float2(aA[3]); v = __half22float2(aB[3]);
                s3 = (u.x + u.y) + (v.x + v.y);
            }
#pragma unroll
            for (int o = 16; o > 0; o >>= 1) {
                s0 += __shfl_xor_sync(0xffffffffu, s0, o);
                s1 += __shfl_xor_sync(0xffffffffu, s1, o);
                s2 += __shfl_xor_sync(0xffffffffu, s2, o);
                s3 += __shfl_xor_sync(0xffffffffu, s3, o);
            }
            if (l == 0) {
                float* dst = s_w + wq * 256 + et * ETILE + e0;
                dst[0] = s0; dst[1] = s1; dst[2] = s2; dst[3] = s3;
            }
        }
        __syncthreads();   // all reads of buf[et&1] done before overwrite
    }

    // ---- prefetch first two phase-2 tiles (overlaps with softmax) ----
    const char* encb = (const char*)(enc + (size_t)b * SENC * DIM);
    {
#pragma unroll
        for (int i = 0; i < 8; i++)
            cp16(sb[0] + (t + 256 * i) * 16, encb + (size_t)(t + 256 * i) * 16);
        cp_commit();
#pragma unroll
        for (int i = 0; i < 8; i++)
            cp16(sb[1] + (t + 256 * i) * 16,
                 encb + (size_t)FTILE * DIM * 4 + (size_t)(t + 256 * i) * 16);
        cp_commit();
    }
    __syncthreads();   // s_w visible to all

    // ---- softmax over 256 encoder positions, 128 threads per q ----
    int qs = t >> 7, idx = t & 127;
    float v0 = s_w[qs * 256 + idx], v1 = s_w[qs * 256 + idx + 128];
    float m = fmaxf(v0, v1);
#pragma unroll
    for (int o = 16; o > 0; o >>= 1)
        m = fmaxf(m, __shfl_xor_sync(0xffffffffu, m, o));
    if (l == 0) s_red[w] = m;
    __syncthreads();
    m = fmaxf(fmaxf(s_red[qs * 4], s_red[qs * 4 + 1]),
              fmaxf(s_red[qs * 4 + 2], s_red[qs * 4 + 3]));
    float e0 = __expf(v0 - m), e1 = __expf(v1 - m);
    float sum = e0 + e1;
#pragma unroll
    for (int o = 16; o > 0; o >>= 1)
        sum += __shfl_xor_sync(0xffffffffu, sum, o);
    if (l == 0) s_red[8 + w] = sum;
    __syncthreads();
    float inv = 1.f / (s_red[8 + qs * 4] + s_red[8 + qs * 4 + 1] +
                       s_red[8 + qs * 4 + 2] + s_red[8 + qs * 4 + 3]);
    s_w[qs * 256 + idx]       = e0 * inv;
    s_w[qs * 256 + idx + 128] = e1 * inv;
    __syncthreads();

    // ---- phase 2: contexts = weights @ encodings (double-buffered) ----
    const int NT2 = SENC / FTILE;   // 16
    int q2 = qs, g = idx;           // q within pair, float4-dim index
    float acc[4] = {};
    for (int ft = 0; ft < NT2; ft++) {
        if (ft + 1 < NT2) cp_wait<1>(); else cp_wait<0>();
        __syncthreads();
        const float4* cur = (const float4*)buf[ft & 1];
        const float* wrow = s_w + q2 * 256 + ft * FTILE;
#pragma unroll 4
        for (int el = 0; el < FTILE; el++) {
            float wgt = wrow[el];
            float4 x = cur[el * 128 + g];
            acc[0] = fmaf(wgt, x.x, acc[0]);
            acc[1] = fmaf(wgt, x.y, acc[1]);
            acc[2] = fmaf(wgt, x.z, acc[2]);
            acc[3] = fmaf(wgt, x.w, acc[3]);
        }
        __syncthreads();   // done reading buf[ft&1]
        if (ft + 2 < NT2) {
            const char* src = encb + (size_t)(ft + 2) * FTILE * DIM * 4;
            unsigned d = sb[ft & 1];
#pragma unroll
            for (int i = 0; i < 8; i++)
                cp16(d + (t + 256 * i) * 16, src + (size_t)(t + 256 * i) * 16);
            cp_commit();
        }
    }

    float* orow = out + (size_t)(b * SDEC + qg * QG + q2) * DIM;
    *(float4*)(orow + 4 * g) = make_float4(acc[0], acc[1], acc[2], acc[3]);
}

// ------------------------- launch ------------------------------------------
extern "C" void kernel_launch(void* const* d_in, const int* in_sizes, int n_in,
                              void* d_out, int out_size)
{
    (void)in_sizes; (void)n_in; (void)out_size;
    const float* enc    = (const float*)d_in[0];
    const float* dec    = (const float*)d_in[1];
    const float* Wenc   = (const float*)d_in[2];
    const float* Wdec   = (const float*)d_in[3];
    const float* Wscore = (const float*)d_in[4];
    const float* benc   = (const float*)d_in[5];
    const float* bdec   = (const float*)d_in[6];
    float* out = (float*)d_out;

    proj2<<<dim3(48, 8), 256>>>(enc, dec, Wenc, Wdec, benc, bdec);

    const int SMEM = 2 * BUFB + QG * 256 * 4;   // 67584
    cudaFuncSetAttribute(fused_attn,
                         cudaFuncAttributeMaxDynamicSharedMemorySize, SMEM);
    fused_attn<<<dim3(SDEC / QG, B_), 256, SMEM>>>(enc, Wscore, out);
}